// round 16
// baseline (speedup 1.0000x reference)
#include <cuda_runtime.h>
#include <cuda_fp16.h>
#include <cstdint>

#define N_NODES 100000
#define D 128
#define E_MAX 600000
#define TILE_M 64
#define NUM_TILES ((N_NODES + TILE_M - 1) / TILE_M)   // 1563
#define THREADS 256
#define GRID_GEMM 152
#define PITCH_H 272
#define SCAN_B 1024
#define NUM_SB ((N_NODES + SCAN_B - 1) / SCAN_B)      // 98
#define CVT_BLOCKS ((N_NODES * (D / 8) + 255) / 256)  // 6250

__device__ uint32_t g_xh[(size_t)N_NODES * 64];       // x rows as half2 (256B/row)
__device__ uint32_t g_apack[(size_t)N_NODES * 128];   // packed fp16 [a|m], fragment order
__device__ uint32_t g_cnt[N_NODES];                   // zero at call start (invariant)
__device__ uint32_t g_cur[N_NODES];                   // per-node degree (set by scan1)
__device__ uint32_t g_base[N_NODES];                  // final start index
__device__ uint32_t g_rank[E_MAX];                    // per-edge rank within its node
__device__ uint32_t g_total;
__device__ uint2    g_edge[E_MAX];

__device__ __forceinline__ uint32_t packh2(float lo, float hi) {
    __half2 h = __floats2half2_rn(lo, hi);
    return *reinterpret_cast<uint32_t*>(&h);
}

__device__ __forceinline__ uint32_t smem_u32(const void* p) {
    uint32_t a;
    asm("{ .reg .u64 t; cvta.to.shared.u64 t, %1; cvt.u32.u64 %0, t; }" : "=r"(a) : "l"(p));
    return a;
}

__device__ __forceinline__ void mma_f16(float* d, uint32_t a0, uint32_t a1,
                                        uint32_t a2, uint32_t a3,
                                        uint32_t b0, uint32_t b1) {
    asm volatile(
        "mma.sync.aligned.m16n8k16.row.col.f32.f16.f16.f32 "
        "{%0,%1,%2,%3}, {%4,%5,%6,%7}, {%8,%9}, {%0,%1,%2,%3};"
        : "+f"(d[0]), "+f"(d[1]), "+f"(d[2]), "+f"(d[3])
        : "r"(a0), "r"(a1), "r"(a2), "r"(a3), "r"(b0), "r"(b1));
}

__device__ __forceinline__ void pack16(uint32_t* u, const float* v) {
    u[0] = packh2(v[0], v[1]);   u[1] = packh2(v[8], v[9]);
    u[2] = packh2(v[2], v[3]);   u[3] = packh2(v[10], v[11]);
    u[4] = packh2(v[4], v[5]);   u[5] = packh2(v[12], v[13]);
    u[6] = packh2(v[6], v[7]);   u[7] = packh2(v[14], v[15]);
}

// ---------------- prep: cvt (x->fp16) + hist-with-rank, fused ----------------
__global__ void prep_kernel(const float* __restrict__ x,
                            const int* __restrict__ ei, int E) {
    int b = blockIdx.x;
    if (b < CVT_BLOCKS) {
        int idx = b * 256 + threadIdx.x;
        if (idx < N_NODES * (D / 8)) {
            const float4* xp = (const float4*)x;
            float4 v0 = xp[idx * 2], v1 = xp[idx * 2 + 1];
            uint4 u = make_uint4(packh2(v0.x, v0.y), packh2(v0.z, v0.w),
                                 packh2(v1.x, v1.y), packh2(v1.z, v1.w));
            ((uint4*)g_xh)[idx] = u;
        }
    } else {
        int e = (b - CVT_BLOCKS) * 256 + threadIdx.x;
        if (e == 0) g_total = 0;
        if (e < E) {
            g_rank[e] = atomicAdd(&g_cnt[ei[E + e]], 1u);
        }
    }
}

__global__ void __launch_bounds__(SCAN_B) scan1_kernel() {
    __shared__ uint32_t s[SCAN_B];
    __shared__ uint32_t base_sh;
    int gi = blockIdx.x * SCAN_B + threadIdx.x;
    uint32_t v = (gi < N_NODES) ? g_cnt[gi] : 0u;
    s[threadIdx.x] = v;
    __syncthreads();
    uint32_t sum = v;
#pragma unroll
    for (int off = 1; off < SCAN_B; off <<= 1) {
        uint32_t t = (threadIdx.x >= off) ? s[threadIdx.x - off] : 0u;
        __syncthreads();
        sum += t;
        s[threadIdx.x] = sum;
        __syncthreads();
    }
    if (threadIdx.x == SCAN_B - 1) base_sh = atomicAdd(&g_total, sum);
    __syncthreads();
    if (gi < N_NODES) {
        g_base[gi] = base_sh + sum - v;
        g_cur[gi] = v;
        g_cnt[gi] = 0;
    }
}

__global__ void fill_kernel(const int* __restrict__ ei,
                            const float* __restrict__ ew, int E) {
    int e = blockIdx.x * blockDim.x + threadIdx.x;
    if (e >= E) return;
    int col = ei[E + e];
    uint32_t slot = g_base[col] + g_rank[e];
    g_edge[slot] = make_uint2((uint32_t)ei[e], __float_as_uint(ew[e]));
}

// ---------------- gather: smem-staged edge records, 4-wide row loads ----------------
__global__ void __launch_bounds__(256) gather_kernel() {
    __shared__ uint2 srec[8][32];
    int w = threadIdx.x >> 5;
    int node = blockIdx.x * 8 + w;
    if (node >= N_NODES) return;
    int lane = threadIdx.x & 31;
    uint32_t start = g_base[node];
    uint32_t cnt = g_cur[node];
    const char* xb = (const char*)g_xh;
    const uint32_t loff = (uint32_t)lane << 3;   // 8B per lane

    float4 a0 = make_float4(0.f, 0.f, 0.f, 0.f);
    float4 a1 = a0, a2 = a0, a3 = a0;

    for (uint32_t base = 0; base < cnt; base += 32) {
        uint32_t rem = cnt - base;
        if (rem > 32) rem = 32;
        // one coalesced load per warp: records for this chunk -> smem
        if (lane < rem) srec[w][lane] = g_edge[start + base + lane];
        __syncwarp();

        uint32_t i = 0;
        for (; i + 4 <= rem; i += 4) {
            uint2 e0 = srec[w][i],     e1 = srec[w][i + 1];
            uint2 e2 = srec[w][i + 2], e3 = srec[w][i + 3];
            uint2 r0 = *(const uint2*)(xb + ((e0.x << 8) + loff));
            uint2 r1 = *(const uint2*)(xb + ((e1.x << 8) + loff));
            uint2 r2 = *(const uint2*)(xb + ((e2.x << 8) + loff));
            uint2 r3 = *(const uint2*)(xb + ((e3.x << 8) + loff));
            float w0 = __uint_as_float(e0.y), w1 = __uint_as_float(e1.y);
            float w2 = __uint_as_float(e2.y), w3 = __uint_as_float(e3.y);
            float2 f;
            f = __half22float2(*(__half2*)&r0.x); a0.x += w0 * f.x; a0.y += w0 * f.y;
            f = __half22float2(*(__half2*)&r0.y); a0.z += w0 * f.x; a0.w += w0 * f.y;
            f = __half22float2(*(__half2*)&r1.x); a1.x += w1 * f.x; a1.y += w1 * f.y;
            f = __half22float2(*(__half2*)&r1.y); a1.z += w1 * f.x; a1.w += w1 * f.y;
            f = __half22float2(*(__half2*)&r2.x); a2.x += w2 * f.x; a2.y += w2 * f.y;
            f = __half22float2(*(__half2*)&r2.y); a2.z += w2 * f.x; a2.w += w2 * f.y;
            f = __half22float2(*(__half2*)&r3.x); a3.x += w3 * f.x; a3.y += w3 * f.y;
            f = __half22float2(*(__half2*)&r3.y); a3.z += w3 * f.x; a3.w += w3 * f.y;
        }
        if (i + 2 <= rem) {
            uint2 e0 = srec[w][i], e1 = srec[w][i + 1];
            uint2 r0 = *(const uint2*)(xb + ((e0.x << 8) + loff));
            uint2 r1 = *(const uint2*)(xb + ((e1.x << 8) + loff));
            float w0 = __uint_as_float(e0.y), w1 = __uint_as_float(e1.y);
            float2 f;
            f = __half22float2(*(__half2*)&r0.x); a0.x += w0 * f.x; a0.y += w0 * f.y;
            f = __half22float2(*(__half2*)&r0.y); a0.z += w0 * f.x; a0.w += w0 * f.y;
            f = __half22float2(*(__half2*)&r1.x); a1.x += w1 * f.x; a1.y += w1 * f.y;
            f = __half22float2(*(__half2*)&r1.y); a1.z += w1 * f.x; a1.w += w1 * f.y;
            i += 2;
        }
        if (i < rem) {
            uint2 e0 = srec[w][i];
            uint2 r0 = *(const uint2*)(xb + ((e0.x << 8) + loff));
            float w0 = __uint_as_float(e0.y);
            float2 f;
            f = __half22float2(*(__half2*)&r0.x); a0.x += w0 * f.x; a0.y += w0 * f.y;
            f = __half22float2(*(__half2*)&r0.y); a0.z += w0 * f.x; a0.w += w0 * f.y;
        }
        __syncwarp();
    }
    a0.x += a1.x + a2.x + a3.x;
    a0.y += a1.y + a2.y + a3.y;
    a0.z += a1.z + a2.z + a3.z;
    a0.w += a1.w + a2.w + a3.w;

    // a = agg + x, m = agg * x (f16x2), pack fragment order
    uint2 rx = *(const uint2*)(xb + (((uint32_t)node << 8) + loff));
    uint32_t gh0, gh1;
    asm("cvt.rn.f16x2.f32 %0, %1, %2;" : "=r"(gh0) : "f"(a0.y), "f"(a0.x));
    asm("cvt.rn.f16x2.f32 %0, %1, %2;" : "=r"(gh1) : "f"(a0.w), "f"(a0.z));
    uint32_t pa0, pa1, pm0, pm1;
    asm("add.rn.f16x2 %0, %1, %2;" : "=r"(pa0) : "r"(gh0), "r"(rx.x));
    asm("add.rn.f16x2 %0, %1, %2;" : "=r"(pa1) : "r"(gh1), "r"(rx.y));
    asm("mul.rn.f16x2 %0, %1, %2;" : "=r"(pm0) : "r"(gh0), "r"(rx.x));
    asm("mul.rn.f16x2 %0, %1, %2;" : "=r"(pm1) : "r"(gh1), "r"(rx.y));

    int o  = lane >> 2;
    int l3 = lane & 3;
    int s0 = (l3 == 0) ? 0 : (l3 == 1) ? 4 : (l3 == 2) ? 1 : 5;
    uint32_t* dst = g_apack + (size_t)node * 128 + o * 8;
    dst[s0]          = pa0;
    dst[s0 + 2]      = pa1;
    dst[64 + s0]     = pm0;
    dst[64 + s0 + 2] = pm1;
}

// ---------------- fp16 m16n8k16 dual-GEMM, cp.async double-buffered ----------------
__device__ __forceinline__ void copy_tile_async(int t, uint32_t as_base,
                                                const int* r_it, const int* o_it,
                                                const uint32_t* dstoff) {
#pragma unroll
    for (int it = 0; it < 4; it++) {
        int row = t * TILE_M + r_it[it];
        if (row >= N_NODES) row = N_NODES - 1;
        const uint32_t* src = g_apack + (size_t)row * 128 + o_it[it] * 8;
        uint32_t d = as_base + dstoff[it];
        asm volatile("cp.async.cg.shared.global [%0], [%1], 16;" :: "r"(d), "l"(src));
        asm volatile("cp.async.cg.shared.global [%0], [%1], 16;" :: "r"(d + 16), "l"(src + 4));
    }
}

__global__ void __launch_bounds__(THREADS, 1)
gemm_kernel(const float* __restrict__ W1, const float* __restrict__ b1,
            const float* __restrict__ W2, const float* __restrict__ b2,
            float* __restrict__ out) {
    extern __shared__ char smc[];
    uint16_t* Ws  = (uint16_t*)smc;                      // [128][PITCH_H]
    uint16_t* As0 = Ws + 128 * PITCH_H;
    uint16_t* As1 = As0 + TILE_M * PITCH_H;
    float* bias   = (float*)(As1 + TILE_M * PITCH_H);

    const int tid  = threadIdx.x;
    const int lane = tid & 31;
    const int wid  = tid >> 5;
    const int wrow = wid >> 2;
    const int wcol = wid & 3;
    const int g    = lane >> 2;
    const int tg   = lane & 3;

    for (int i = tid; i < 128 * 16; i += THREADS) {
        int c = i >> 4, o = i & 15;
        const float* src = (o < 8) ? (W1 + c * 128 + o * 16)
                                   : (W2 + c * 128 + (o - 8) * 16);
        float v[16];
        *(float4*)&v[0]  = *(const float4*)(src);
        *(float4*)&v[4]  = *(const float4*)(src + 4);
        *(float4*)&v[8]  = *(const float4*)(src + 8);
        *(float4*)&v[12] = *(const float4*)(src + 12);
        uint32_t u[8];
        pack16(u, v);
        uint32_t* dst = (uint32_t*)&Ws[c * PITCH_H + o * 16];
        *(uint4*)dst = *(uint4*)&u[0];
        *(uint4*)(dst + 4) = *(uint4*)&u[4];
    }
    for (int i = tid; i < 128; i += THREADS) bias[i] = b1[i] + b2[i];
    __syncthreads();

    float bias_c[4][2];
#pragma unroll
    for (int nf = 0; nf < 4; nf++) {
        int col = wcol * 32 + nf * 8 + tg * 2;
        bias_c[nf][0] = bias[col];
        bias_c[nf][1] = bias[col + 1];
    }

    const int rb = wrow * 32;
    const char* WsB = (const char*)Ws;
    uint16_t* Asp[2] = {As0, As1};
    uint32_t as_u32[2] = {smem_u32(As0), smem_u32(As1)};

    int r_it[4], o_it[4];
    uint32_t dstoff[4];
#pragma unroll
    for (int it = 0; it < 4; it++) {
        int idx = it * THREADS + tid;
        r_it[it] = idx >> 4;
        o_it[it] = idx & 15;
        dstoff[it] = (uint32_t)((r_it[it] * PITCH_H + o_it[it] * 16) * 2);
    }

    int buf = 0;
    int t = blockIdx.x;
    if (t < NUM_TILES) {
        copy_tile_async(t, as_u32[0], r_it, o_it, dstoff);
        asm volatile("cp.async.commit_group;");
    }

    for (; t < NUM_TILES; t += GRID_GEMM) {
        asm volatile("cp.async.wait_group 0;");
        __syncthreads();

        int tn = t + GRID_GEMM;
        if (tn < NUM_TILES) {
            copy_tile_async(tn, as_u32[buf ^ 1], r_it, o_it, dstoff);
            asm volatile("cp.async.commit_group;");
        }

        const char* AsB = (const char*)Asp[buf];

        float acc[2][4][4];
#pragma unroll
        for (int mf = 0; mf < 2; mf++)
#pragma unroll
            for (int nf = 0; nf < 4; nf++)
#pragma unroll
                for (int j = 0; j < 4; j++) acc[mf][nf][j] = 0.f;

#pragma unroll
        for (int ks = 0; ks < 16; ks++) {
            const int goff = ks * 32 + tg * 8;
            uint2 aLo[2], aHi[2];
#pragma unroll
            for (int mf = 0; mf < 2; mf++) {
                int rbyte = (rb + mf * 16 + g) * PITCH_H * 2;
                aLo[mf] = *(const uint2*)(AsB + rbyte + goff);
                aHi[mf] = *(const uint2*)(AsB + rbyte + 8 * PITCH_H * 2 + goff);
            }
#pragma unroll
            for (int nf = 0; nf < 4; nf++) {
                int cbyte = (wcol * 32 + nf * 8 + g) * PITCH_H * 2;
                uint2 bf = *(const uint2*)(WsB + cbyte + goff);
                mma_f16(acc[0][nf], aLo[0].x, aHi[0].x, aLo[0].y, aHi[0].y, bf.x, bf.y);
                mma_f16(acc[1][nf], aLo[1].x, aHi[1].x, aLo[1].y, aHi[1].y, bf.x, bf.y);
            }
        }

#pragma unroll
        for (int mf = 0; mf < 2; mf++) {
            int row0 = t * TILE_M + rb + mf * 16 + g;
            int row1 = row0 + 8;
#pragma unroll
            for (int nf = 0; nf < 4; nf++) {
                int col = wcol * 32 + nf * 8 + tg * 2;
                float h0 = acc[mf][nf][0] + bias_c[nf][0];
                float h1 = acc[mf][nf][1] + bias_c[nf][1];
                float h2 = acc[mf][nf][2] + bias_c[nf][0];
                float h3 = acc[mf][nf][3] + bias_c[nf][1];
                float2 v0 = make_float2(h0 > 0.f ? h0 : 0.2f * h0,
                                        h1 > 0.f ? h1 : 0.2f * h1);
                float2 v1 = make_float2(h2 > 0.f ? h2 : 0.2f * h2,
                                        h3 > 0.f ? h3 : 0.2f * h3);
                if (row0 < N_NODES) *(float2*)(out + (size_t)row0 * D + col) = v0;
                if (row1 < N_NODES) *(float2*)(out + (size_t)row1 * D + col) = v1;
            }
        }
        buf ^= 1;
    }
}

extern "C" void kernel_launch(void* const* d_in, const int* in_sizes, int n_in,
                              void* d_out, int out_size) {
    const float* x  = (const float*)d_in[0];
    const int*   ei = (const int*)d_in[1];
    const float* ew = (const float*)d_in[2];
    const float* W1 = (const float*)d_in[3];
    const float* b1 = (const float*)d_in[4];
    const float* W2 = (const float*)d_in[5];
    const float* b2 = (const float*)d_in[6];
    float* out = (float*)d_out;

    int E = in_sizes[2];

    int prep_grid = CVT_BLOCKS + (E + 255) / 256;
    prep_kernel<<<prep_grid, 256>>>(x, ei, E);
    scan1_kernel<<<NUM_SB, SCAN_B>>>();
    fill_kernel<<<(E + 255) / 256, 256>>>(ei, ew, E);
    gather_kernel<<<(N_NODES + 7) / 8, 256>>>();

    const int smem_bytes = (128 + 2 * TILE_M) * PITCH_H * 2 + 128 * 4;
    cudaFuncSetAttribute(gemm_kernel,
                         cudaFuncAttributeMaxDynamicSharedMemorySize, smem_bytes);
    gemm_kernel<<<GRID_GEMM, THREADS, smem_bytes>>>(W1, b1, W2, b2, out);
}

// round 17
// speedup vs baseline: 1.2073x; 1.2073x over previous
#include <cuda_runtime.h>
#include <cuda_fp16.h>
#include <cstdint>

#define N_NODES 100000
#define D 128
#define E_MAX 600000
#define TILE_M 64
#define NUM_TILES ((N_NODES + TILE_M - 1) / TILE_M)   // 1563
#define THREADS 256
#define GRID_GEMM 152
#define PITCH_H 272
#define FBLOCKS 912                    // 6 CTAs/SM x 152 SMs, co-resident
#define FTHREADS (FBLOCKS * 256)
#define SCAN_CHUNK 256
#define SCAN_BLOCKS ((N_NODES + SCAN_CHUNK - 1) / SCAN_CHUNK)   // 391

__device__ uint32_t g_xh[(size_t)N_NODES * 64];       // x rows as half2 (256B/row)
__device__ uint32_t g_apack[(size_t)N_NODES * 128];   // packed fp16 [a|m], fragment order
__device__ uint32_t g_cnt[N_NODES];                   // zero at call start (invariant)
__device__ uint32_t g_cur[N_NODES];                   // per-node degree
__device__ uint32_t g_base[N_NODES];                  // final start index
__device__ uint32_t g_rank[E_MAX];                    // per-edge rank within its node
__device__ uint32_t g_total;
__device__ uint2    g_edge[E_MAX];
__device__ uint32_t g_sync_cnt;                       // barrier arrivals (0 between barriers)
__device__ uint32_t g_sync_gen;                       // barrier generation (monotonic)

__device__ __forceinline__ uint32_t packh2(float lo, float hi) {
    __half2 h = __floats2half2_rn(lo, hi);
    return *reinterpret_cast<uint32_t*>(&h);
}

__device__ __forceinline__ uint32_t smem_u32(const void* p) {
    uint32_t a;
    asm("{ .reg .u64 t; cvta.to.shared.u64 t, %1; cvt.u32.u64 %0, t; }" : "=r"(a) : "l"(p));
    return a;
}

__device__ __forceinline__ void mma_f16(float* d, uint32_t a0, uint32_t a1,
                                        uint32_t a2, uint32_t a3,
                                        uint32_t b0, uint32_t b1) {
    asm volatile(
        "mma.sync.aligned.m16n8k16.row.col.f32.f16.f16.f32 "
        "{%0,%1,%2,%3}, {%4,%5,%6,%7}, {%8,%9}, {%0,%1,%2,%3};"
        : "+f"(d[0]), "+f"(d[1]), "+f"(d[2]), "+f"(d[3])
        : "r"(a0), "r"(a1), "r"(a2), "r"(a3), "r"(b0), "r"(b1));
}

__device__ __forceinline__ void pack16(uint32_t* u, const float* v) {
    u[0] = packh2(v[0], v[1]);   u[1] = packh2(v[8], v[9]);
    u[2] = packh2(v[2], v[3]);   u[3] = packh2(v[10], v[11]);
    u[4] = packh2(v[4], v[5]);   u[5] = packh2(v[12], v[13]);
    u[6] = packh2(v[6], v[7]);   u[7] = packh2(v[14], v[15]);
}

// generation-based grid barrier: all FBLOCKS blocks co-resident by launch_bounds
__device__ __forceinline__ void grid_sync() {
    __syncthreads();
    if (threadIdx.x == 0) {
        __threadfence();
        uint32_t gen = *(volatile uint32_t*)&g_sync_gen;
        uint32_t t = atomicAdd(&g_sync_cnt, 1u);
        if (t == FBLOCKS - 1) {
            g_sync_cnt = 0;
            __threadfence();
            *(volatile uint32_t*)&g_sync_gen = gen + 1;
        } else {
            while (*(volatile uint32_t*)&g_sync_gen == gen) __nanosleep(64);
        }
        __threadfence();
    }
    __syncthreads();
}

// ---------------- fused CSR build + gather (persistent, 1 launch) ----------------
__global__ void __launch_bounds__(256, 6)
fused_kernel(const float* __restrict__ x,
             const int* __restrict__ ei,
             const float* __restrict__ ew, int E) {
    const int tid = threadIdx.x;
    const int gtid = blockIdx.x * 256 + tid;

    if (gtid == 0) g_total = 0;

    // ---- phase 1: cvt x -> fp16 rows, and hist with rank ----
    {
        const float4* xp = (const float4*)x;
        for (int idx = gtid; idx < N_NODES * (D / 8); idx += FTHREADS) {
            float4 v0 = xp[idx * 2], v1 = xp[idx * 2 + 1];
            uint4 u = make_uint4(packh2(v0.x, v0.y), packh2(v0.z, v0.w),
                                 packh2(v1.x, v1.y), packh2(v1.z, v1.w));
            ((uint4*)g_xh)[idx] = u;
        }
        for (int e = gtid; e < E; e += FTHREADS)
            g_rank[e] = atomicAdd(&g_cnt[ei[E + e]], 1u);
    }
    grid_sync();

    // ---- phase 2: block-local scan + atomic base (blocks 0..SCAN_BLOCKS-1) ----
    if (blockIdx.x < SCAN_BLOCKS) {
        __shared__ uint32_t s[SCAN_CHUNK];
        __shared__ uint32_t base_sh;
        int gi = blockIdx.x * SCAN_CHUNK + tid;
        uint32_t v = (gi < N_NODES) ? g_cnt[gi] : 0u;
        s[tid] = v;
        __syncthreads();
        uint32_t sum = v;
#pragma unroll
        for (int off = 1; off < SCAN_CHUNK; off <<= 1) {
            uint32_t t = (tid >= off) ? s[tid - off] : 0u;
            __syncthreads();
            sum += t;
            s[tid] = sum;
            __syncthreads();
        }
        if (tid == SCAN_CHUNK - 1) base_sh = atomicAdd(&g_total, sum);
        __syncthreads();
        if (gi < N_NODES) {
            g_base[gi] = base_sh + sum - v;
            g_cur[gi] = v;
            g_cnt[gi] = 0;
        }
    }
    grid_sync();

    // ---- phase 3: fill (atomic-free) ----
    for (int e = gtid; e < E; e += FTHREADS) {
        int col = ei[E + e];
        uint32_t slot = g_base[col] + g_rank[e];
        g_edge[slot] = make_uint2((uint32_t)ei[e], __float_as_uint(ew[e]));
    }
    grid_sync();

    // ---- phase 4: gather (r12-form) + fused a/m fp16 pack ----
    {
        const int lane = tid & 31;
        const int wgid = blockIdx.x * 8 + (tid >> 5);
        const char* xb = (const char*)g_xh;
        const uint32_t loff = (uint32_t)lane << 3;

        for (int node = wgid; node < N_NODES; node += FBLOCKS * 8) {
            uint32_t start = g_base[node];
            uint32_t cnt = g_cur[node];
            float4 acc = make_float4(0.f, 0.f, 0.f, 0.f);
            float4 acc2 = acc;
            uint32_t i = 0;
            for (; i + 2 <= cnt; i += 2) {
                uint2 e0 = g_edge[start + i];
                uint2 e1 = g_edge[start + i + 1];
                uint2 r0 = *(const uint2*)(xb + ((e0.x << 8) + loff));
                uint2 r1 = *(const uint2*)(xb + ((e1.x << 8) + loff));
                float w0 = __uint_as_float(e0.y);
                float w1 = __uint_as_float(e1.y);
                float2 f00 = __half22float2(*(__half2*)&r0.x);
                float2 f01 = __half22float2(*(__half2*)&r0.y);
                float2 f10 = __half22float2(*(__half2*)&r1.x);
                float2 f11 = __half22float2(*(__half2*)&r1.y);
                acc.x += w0 * f00.x; acc.y += w0 * f00.y;
                acc.z += w0 * f01.x; acc.w += w0 * f01.y;
                acc2.x += w1 * f10.x; acc2.y += w1 * f10.y;
                acc2.z += w1 * f11.x; acc2.w += w1 * f11.y;
            }
            if (i < cnt) {
                uint2 e0 = g_edge[start + i];
                uint2 r0 = *(const uint2*)(xb + ((e0.x << 8) + loff));
                float w0 = __uint_as_float(e0.y);
                float2 f00 = __half22float2(*(__half2*)&r0.x);
                float2 f01 = __half22float2(*(__half2*)&r0.y);
                acc.x += w0 * f00.x; acc.y += w0 * f00.y;
                acc.z += w0 * f01.x; acc.w += w0 * f01.y;
            }
            acc.x += acc2.x; acc.y += acc2.y; acc.z += acc2.z; acc.w += acc2.w;

            uint2 rx = *(const uint2*)(xb + (((uint32_t)node << 8) + loff));
            uint32_t gh0, gh1;
            asm("cvt.rn.f16x2.f32 %0, %1, %2;" : "=r"(gh0) : "f"(acc.y), "f"(acc.x));
            asm("cvt.rn.f16x2.f32 %0, %1, %2;" : "=r"(gh1) : "f"(acc.w), "f"(acc.z));
            uint32_t a0, a1, m0, m1;
            asm("add.rn.f16x2 %0, %1, %2;" : "=r"(a0) : "r"(gh0), "r"(rx.x));
            asm("add.rn.f16x2 %0, %1, %2;" : "=r"(a1) : "r"(gh1), "r"(rx.y));
            asm("mul.rn.f16x2 %0, %1, %2;" : "=r"(m0) : "r"(gh0), "r"(rx.x));
            asm("mul.rn.f16x2 %0, %1, %2;" : "=r"(m1) : "r"(gh1), "r"(rx.y));

            int o  = lane >> 2;
            int l3 = lane & 3;
            int s0 = (l3 == 0) ? 0 : (l3 == 1) ? 4 : (l3 == 2) ? 1 : 5;
            uint32_t* dst = g_apack + (size_t)node * 128 + o * 8;
            dst[s0]          = a0;
            dst[s0 + 2]      = a1;
            dst[64 + s0]     = m0;
            dst[64 + s0 + 2] = m1;
        }
    }
}

// ---------------- fp16 m16n8k16 dual-GEMM, cp.async double-buffered ----------------
__device__ __forceinline__ void copy_tile_async(int t, uint32_t as_base,
                                                const int* r_it, const int* o_it,
                                                const uint32_t* dstoff) {
#pragma unroll
    for (int it = 0; it < 4; it++) {
        int row = t * TILE_M + r_it[it];
        if (row >= N_NODES) row = N_NODES - 1;
        const uint32_t* src = g_apack + (size_t)row * 128 + o_it[it] * 8;
        uint32_t d = as_base + dstoff[it];
        asm volatile("cp.async.cg.shared.global [%0], [%1], 16;" :: "r"(d), "l"(src));
        asm volatile("cp.async.cg.shared.global [%0], [%1], 16;" :: "r"(d + 16), "l"(src + 4));
    }
}

__global__ void __launch_bounds__(THREADS, 1)
gemm_kernel(const float* __restrict__ W1, const float* __restrict__ b1,
            const float* __restrict__ W2, const float* __restrict__ b2,
            float* __restrict__ out) {
    extern __shared__ char smc[];
    uint16_t* Ws  = (uint16_t*)smc;                      // [128][PITCH_H]
    uint16_t* As0 = Ws + 128 * PITCH_H;
    uint16_t* As1 = As0 + TILE_M * PITCH_H;
    float* bias   = (float*)(As1 + TILE_M * PITCH_H);

    const int tid  = threadIdx.x;
    const int lane = tid & 31;
    const int wid  = tid >> 5;
    const int wrow = wid >> 2;
    const int wcol = wid & 3;
    const int g    = lane >> 2;
    const int tg   = lane & 3;

    for (int i = tid; i < 128 * 16; i += THREADS) {
        int c = i >> 4, o = i & 15;
        const float* src = (o < 8) ? (W1 + c * 128 + o * 16)
                                   : (W2 + c * 128 + (o - 8) * 16);
        float v[16];
        *(float4*)&v[0]  = *(const float4*)(src);
        *(float4*)&v[4]  = *(const float4*)(src + 4);
        *(float4*)&v[8]  = *(const float4*)(src + 8);
        *(float4*)&v[12] = *(const float4*)(src + 12);
        uint32_t u[8];
        pack16(u, v);
        uint32_t* dst = (uint32_t*)&Ws[c * PITCH_H + o * 16];
        *(uint4*)dst = *(uint4*)&u[0];
        *(uint4*)(dst + 4) = *(uint4*)&u[4];
    }
    for (int i = tid; i < 128; i += THREADS) bias[i] = b1[i] + b2[i];
    __syncthreads();

    float bias_c[4][2];
#pragma unroll
    for (int nf = 0; nf < 4; nf++) {
        int col = wcol * 32 + nf * 8 + tg * 2;
        bias_c[nf][0] = bias[col];
        bias_c[nf][1] = bias[col + 1];
    }

    const int rb = wrow * 32;
    const char* WsB = (const char*)Ws;
    uint16_t* Asp[2] = {As0, As1};
    uint32_t as_u32[2] = {smem_u32(As0), smem_u32(As1)};

    int r_it[4], o_it[4];
    uint32_t dstoff[4];
#pragma unroll
    for (int it = 0; it < 4; it++) {
        int idx = it * THREADS + tid;
        r_it[it] = idx >> 4;
        o_it[it] = idx & 15;
        dstoff[it] = (uint32_t)((r_it[it] * PITCH_H + o_it[it] * 16) * 2);
    }

    int buf = 0;
    int t = blockIdx.x;
    if (t < NUM_TILES) {
        copy_tile_async(t, as_u32[0], r_it, o_it, dstoff);
        asm volatile("cp.async.commit_group;");
    }

    for (; t < NUM_TILES; t += GRID_GEMM) {
        asm volatile("cp.async.wait_group 0;");
        __syncthreads();

        int tn = t + GRID_GEMM;
        if (tn < NUM_TILES) {
            copy_tile_async(tn, as_u32[buf ^ 1], r_it, o_it, dstoff);
            asm volatile("cp.async.commit_group;");
        }

        const char* AsB = (const char*)Asp[buf];

        float acc[2][4][4];
#pragma unroll
        for (int mf = 0; mf < 2; mf++)
#pragma unroll
            for (int nf = 0; nf < 4; nf++)
#pragma unroll
                for (int j = 0; j < 4; j++) acc[mf][nf][j] = 0.f;

#pragma unroll
        for (int ks = 0; ks < 16; ks++) {
            const int goff = ks * 32 + tg * 8;
            uint2 aLo[2], aHi[2];
#pragma unroll
            for (int mf = 0; mf < 2; mf++) {
                int rbyte = (rb + mf * 16 + g) * PITCH_H * 2;
                aLo[mf] = *(const uint2*)(AsB + rbyte + goff);
                aHi[mf] = *(const uint2*)(AsB + rbyte + 8 * PITCH_H * 2 + goff);
            }
#pragma unroll
            for (int nf = 0; nf < 4; nf++) {
                int cbyte = (wcol * 32 + nf * 8 + g) * PITCH_H * 2;
                uint2 bf = *(const uint2*)(WsB + cbyte + goff);
                mma_f16(acc[0][nf], aLo[0].x, aHi[0].x, aLo[0].y, aHi[0].y, bf.x, bf.y);
                mma_f16(acc[1][nf], aLo[1].x, aHi[1].x, aLo[1].y, aHi[1].y, bf.x, bf.y);
            }
        }

#pragma unroll
        for (int mf = 0; mf < 2; mf++) {
            int row0 = t * TILE_M + rb + mf * 16 + g;
            int row1 = row0 + 8;
#pragma unroll
            for (int nf = 0; nf < 4; nf++) {
                int col = wcol * 32 + nf * 8 + tg * 2;
                float h0 = acc[mf][nf][0] + bias_c[nf][0];
                float h1 = acc[mf][nf][1] + bias_c[nf][1];
                float h2 = acc[mf][nf][2] + bias_c[nf][0];
                float h3 = acc[mf][nf][3] + bias_c[nf][1];
                float2 v0 = make_float2(h0 > 0.f ? h0 : 0.2f * h0,
                                        h1 > 0.f ? h1 : 0.2f * h1);
                float2 v1 = make_float2(h2 > 0.f ? h2 : 0.2f * h2,
                                        h3 > 0.f ? h3 : 0.2f * h3);
                if (row0 < N_NODES) *(float2*)(out + (size_t)row0 * D + col) = v0;
                if (row1 < N_NODES) *(float2*)(out + (size_t)row1 * D + col) = v1;
            }
        }
        buf ^= 1;
    }
}

extern "C" void kernel_launch(void* const* d_in, const int* in_sizes, int n_in,
                              void* d_out, int out_size) {
    const float* x  = (const float*)d_in[0];
    const int*   ei = (const int*)d_in[1];
    const float* ew = (const float*)d_in[2];
    const float* W1 = (const float*)d_in[3];
    const float* b1 = (const float*)d_in[4];
    const float* W2 = (const float*)d_in[5];
    const float* b2 = (const float*)d_in[6];
    float* out = (float*)d_out;

    int E = in_sizes[2];

    fused_kernel<<<FBLOCKS, 256>>>(x, ei, ew, E);

    const int smem_bytes = (128 + 2 * TILE_M) * PITCH_H * 2 + 128 * 4;
    cudaFuncSetAttribute(gemm_kernel,
                         cudaFuncAttributeMaxDynamicSharedMemorySize, smem_bytes);
    gemm_kernel<<<GRID_GEMM, THREADS, smem_bytes>>>(W1, b1, W2, b2, out);
}